// round 6
// baseline (speedup 1.0000x reference)
#include <cuda_runtime.h>
#include <cuda_fp16.h>
#include <cstdint>

#define B_PTS   131072
#define HDIM    256
#define NBLK    8
#define NMID    3
#define MT      32
#define NTHREADS 256
#define NLAYERS (NBLK * NMID)
#define NCHUNK  16            // 16 k-values per chunk
#define CHUNK_BYTES 32768     // [hi 16384 | lo 16384]

// ---------------- shared memory byte map ----------------
#define OFF_AHI  0            // 6 mt x 32 ks x 128 f32 = 98304 B (tf32 hi)
#define OFF_ALO  98304        // same count fp16 (scaled x2048) = 49152 B
#define OFF_B    147456       // 2 x 32768 double buffer
#define OFF_WOS  212992       // 512 floats
#define OFF_ZX   215040       // 64 floats
#define OFF_VV   215296       // 64 floats
#define OFF_DL   215552       // 32 floats
#define OFF_RED  215680       // 192 floats
#define SMEM_BYTES 216448

// pre-split B fragments: per layer 16 chunks x [hi 1024 uint4 | lo 1024 uint4]
__device__ uint4 g_Wf[(size_t)NLAYERS * NCHUNK * 2048];

// ---------------- helpers ----------------
__device__ __forceinline__ uint32_t smem_u32(const void* p) {
    uint32_t a;
    asm("{ .reg .u64 t; cvta.to.shared.u64 t, %1; cvt.u32.u64 %0, t; }" : "=r"(a) : "l"(p));
    return a;
}
__device__ __forceinline__ uint32_t cvt_tf32(float x) {
    uint32_t o;
    asm("cvt.rna.tf32.f32 %0, %1;" : "=r"(o) : "f"(x));
    return o;
}
__device__ __forceinline__ void mma_tf32(float c[4], const uint4& a, uint32_t b0, uint32_t b1) {
    asm volatile("mma.sync.aligned.m16n8k8.row.col.f32.tf32.tf32.f32 "
                 "{%0,%1,%2,%3}, {%4,%5,%6,%7}, {%8,%9}, {%0,%1,%2,%3};"
                 : "+f"(c[0]), "+f"(c[1]), "+f"(c[2]), "+f"(c[3])
                 : "r"(a.x), "r"(a.y), "r"(a.z), "r"(a.w), "r"(b0), "r"(b1));
}
__device__ __forceinline__ void cp16(uint32_t dst, const void* src) {
    asm volatile("cp.async.cg.shared.global [%0], [%1], 16;" :: "r"(dst), "l"(src));
}
#define CP_COMMIT() asm volatile("cp.async.commit_group;" ::: "memory")
#define CP_WAIT1()  asm volatile("cp.async.wait_group 1;"  ::: "memory")
#define CP_WAIT0()  asm volatile("cp.async.wait_group 0;"  ::: "memory")

// split store: hi = rna_tf32(val), lo = fp16((val - hi) * 2048)
__device__ __forceinline__ void store_split(uint32_t* Ahi, __half* Alo, int idx, float val) {
    uint32_t h = cvt_tf32(val);
    Ahi[idx] = h;
    Alo[idx] = __float2half_rn((val - __uint_as_float(h)) * 2048.f);
}
__device__ __forceinline__ float load_full(const uint32_t* Ahi, const __half* Alo, int idx) {
    return __uint_as_float(Ahi[idx]) + __half2float(Alo[idx]) * (1.f / 2048.f);
}

// ---------------- pre-pass: pack Wm into split B-fragment layout ----------------
__global__ void prep_w_kernel(const float* __restrict__ Wm) {
    int g = blockIdx.x * 256 + threadIdx.x;   // 0 .. 393215
    int lane = g & 31;
    int t = g >> 5;
    int ntile = t & 31; t >>= 5;
    int kc    = t & 15; t >>= 4;
    int l     = t;                            // 0..23
    int n  = ntile * 8 + (lane >> 2);
    int k1 = kc * NCHUNK + (lane & 3);
    const float* W = Wm + (size_t)l * HDIM * HDIM;
    uint4 hi, lo;
    #pragma unroll
    for (int i = 0; i < 4; ++i) {
        float w = W[(size_t)(k1 + 4 * i) * HDIM + n];
        uint32_t h = cvt_tf32(w);
        uint32_t s = cvt_tf32(w - __uint_as_float(h));   // unscaled residual (tf32 exp range ok)
        (&hi.x)[i] = h;
        (&lo.x)[i] = s;
    }
    size_t base = (size_t)l * (NCHUNK * 2048) + (size_t)kc * 2048;
    g_Wf[base + (ntile * 32 + lane)]        = hi;
    g_Wf[base + 1024 + (ntile * 32 + lane)] = lo;
}

// A-fragment element index for logical (row 0..95, k 0..255)
__device__ __forceinline__ int afrag_idx(int row, int k) {
    int mt = row >> 4, r15 = row & 15;
    return ((mt * 32 + (k >> 3)) * 128) +
           ((((r15 & 7) << 2) | (k & 3)) << 2) +
           ((r15 >> 3) & 1) + (((k >> 2) & 1) << 1);
}

// ---------------- main kernel ----------------
__global__ void __launch_bounds__(NTHREADS, 1)
eq_resflow_mma(const float* __restrict__ x,  const float* __restrict__ v,
               const float* __restrict__ Wi, const float* __restrict__ bi,
               const float* __restrict__ bm,
               const float* __restrict__ Wo, const float* __restrict__ bo,
               float* __restrict__ out)
{
    extern __shared__ char smem[];
    const uint32_t sb = smem_u32(smem);
    uint32_t* Ahi = (uint32_t*)(smem + OFF_AHI);
    __half*   Alo = (__half*)  (smem + OFF_ALO);
    float* Wos = (float*)(smem + OFF_WOS);
    float* zx  = (float*)(smem + OFF_ZX);
    float* vv  = (float*)(smem + OFF_VV);
    float* dl  = (float*)(smem + OFF_DL);
    float* red = (float*)(smem + OFF_RED);

    const int tid  = threadIdx.x;
    const int w    = tid >> 5;
    const int lane = tid & 31;
    const int pbase = blockIdx.x * MT;

    if (tid < MT) {
        float2 xx = *reinterpret_cast<const float2*>(x + 2 * (pbase + tid));
        float2 vx = *reinterpret_cast<const float2*>(v + 2 * (pbase + tid));
        zx[2 * tid] = xx.x; zx[2 * tid + 1] = xx.y;
        vv[2 * tid] = vx.x; vv[2 * tid + 1] = vx.y;
        dl[tid] = 0.f;
    }
    __syncthreads();

    for (int b = 0; b < NBLK; ++b) {
        // ---------- layer 0 : 2 -> 256, split-write A fragments ----------
        {
            int n = tid;
            float w0 = __ldg(Wi + (size_t)b * 2 * HDIM + n);
            float w1 = __ldg(Wi + (size_t)b * 2 * HDIM + HDIM + n);
            float bb = __ldg(bi + (size_t)b * HDIM + n);
            #pragma unroll 4
            for (int p = 0; p < MT; ++p) {
                float pre = fmaf(zx[2 * p], w0, fmaf(zx[2 * p + 1], w1, bb));
                float m = pre > 0.f ? 1.f : 0.f;
                store_split(Ahi, Alo, afrag_idx(p,      n), fmaxf(pre, 0.f));
                store_split(Ahi, Alo, afrag_idx(32 + p, n), w0 * m);
                store_split(Ahi, Alo, afrag_idx(64 + p, n), w1 * m);
            }
        }
        __syncthreads();   // A ready

        // ---------- 3 mid layers : compensated tf32 mma ----------
        for (int lj = 0; lj < NMID; ++lj) {
            const int glayer = b * NMID + lj;
            const char* wsrc = (const char*)g_Wf + (size_t)glayer * NCHUNK * CHUNK_BYTES;

            // prefetch chunks 0,1  (32768 B each, 128 B per thread)
            #pragma unroll
            for (int pc = 0; pc < 2; ++pc) {
                uint32_t dst = sb + OFF_B + pc * CHUNK_BYTES + tid * 128;
                const char* src = wsrc + (size_t)pc * CHUNK_BYTES + tid * 128;
                #pragma unroll
                for (int i = 0; i < 8; ++i) cp16(dst + i * 16, src + i * 16);
                CP_COMMIT();
            }

            float c[6][4][4];
            #pragma unroll
            for (int mt = 0; mt < 6; ++mt)
                #pragma unroll
                for (int ntl = 0; ntl < 4; ++ntl)
                    #pragma unroll
                    for (int r = 0; r < 4; ++r) c[mt][ntl][r] = 0.f;

            #pragma unroll 1
            for (int kc = 0; kc < NCHUNK; ++kc) {
                if (kc < NCHUNK - 1) CP_WAIT1(); else CP_WAIT0();
                __syncthreads();

                const char* Bb = smem + OFF_B + (kc & 1) * CHUNK_BYTES;
                uint4 bh[4], bl[4];
                #pragma unroll
                for (int ntl = 0; ntl < 4; ++ntl) {
                    int o = (((w * 4 + ntl) * 32 + lane) << 4);
                    bh[ntl] = *(const uint4*)(Bb + o);
                    bl[ntl] = *(const uint4*)(Bb + 16384 + o);
                }
                #pragma unroll
                for (int sub = 0; sub < 2; ++sub) {
                    const int ks = kc * 2 + sub;
                    #pragma unroll
                    for (int mt = 0; mt < 6; ++mt) {
                        const int fi = (mt * 32 + ks) * 128 + lane * 4;
                        uint4 avh = *(const uint4*)(smem + OFF_AHI + (fi << 2));
                        uint2 l2  = *(const uint2*)(smem + OFF_ALO + (fi << 1));
                        float2 f0 = __half22float2(*(const __half2*)&l2.x);
                        float2 f1 = __half22float2(*(const __half2*)&l2.y);
                        uint4 avl;
                        avl.x = __float_as_uint(f0.x * (1.f / 2048.f));
                        avl.y = __float_as_uint(f0.y * (1.f / 2048.f));
                        avl.z = __float_as_uint(f1.x * (1.f / 2048.f));
                        avl.w = __float_as_uint(f1.y * (1.f / 2048.f));
                        #pragma unroll
                        for (int ntl = 0; ntl < 4; ++ntl) {
                            uint32_t bh0 = sub ? bh[ntl].z : bh[ntl].x;
                            uint32_t bh1 = sub ? bh[ntl].w : bh[ntl].y;
                            uint32_t bl0 = sub ? bl[ntl].z : bl[ntl].x;
                            uint32_t bl1 = sub ? bl[ntl].w : bl[ntl].y;
                            mma_tf32(c[mt][ntl], avh, bh0, bh1);   // hi*hi
                            mma_tf32(c[mt][ntl], avh, bl0, bl1);   // hi*lo
                            mma_tf32(c[mt][ntl], avl, bh0, bh1);   // lo*hi
                        }
                    }
                }
                if (kc < NCHUNK - 2) {
                    __syncthreads();
                    uint32_t dst = sb + OFF_B + (kc & 1) * CHUNK_BYTES + tid * 128;
                    const char* src = wsrc + (size_t)(kc + 2) * CHUNK_BYTES + tid * 128;
                    #pragma unroll
                    for (int i = 0; i < 8; ++i) cp16(dst + i * 16, src + i * 16);
                    CP_COMMIT();
                }
            }

            // biases for my 4 n-tiles
            float2 bb2[4];
            #pragma unroll
            for (int ntl = 0; ntl < 4; ++ntl) {
                int n0 = (w * 4 + ntl) * 8 + 2 * (lane & 3);
                bb2[ntl] = *reinterpret_cast<const float2*>(bm + (size_t)glayer * HDIM + n0);
            }
            __syncthreads();   // all warps done reading A

            // epilogue: bias + ReLU on h, mask tangents (register-local), split-write A
            #pragma unroll
            for (int mt = 0; mt < 2; ++mt) {
                #pragma unroll
                for (int ntl = 0; ntl < 4; ++ntl) {
                    #pragma unroll
                    for (int r = 0; r < 4; ++r) {
                        float pre = c[mt][ntl][r] + ((r & 1) ? bb2[ntl].y : bb2[ntl].x);
                        float m = pre > 0.f ? 1.f : 0.f;
                        int row = mt * 16 + (lane >> 2) + ((r >> 1) << 3);
                        int col = (w * 4 + ntl) * 8 + 2 * (lane & 3) + (r & 1);
                        store_split(Ahi, Alo, afrag_idx(row,      col), fmaxf(pre, 0.f));
                        store_split(Ahi, Alo, afrag_idx(row + 32, col), c[mt + 2][ntl][r] * m);
                        store_split(Ahi, Alo, afrag_idx(row + 64, col), c[mt + 4][ntl][r] * m);
                    }
                }
            }
            __syncthreads();
        }

        // ---------- output layer : 256 -> 2, Jacobian, power series ----------
        if (tid < 128)
            ((float4*)Wos)[tid] = ((const float4*)(Wo + (size_t)b * HDIM * 2))[tid];
        __syncthreads();

        if (tid < 192) {   // 32 pts x 3 states x 2 cols
            int p = tid & 31, idx = tid >> 5;
            int s = idx >> 1, cc = idx & 1;
            int row = s * 32 + p;
            float sum = 0.f;
            #pragma unroll 8
            for (int k = 0; k < HDIM; ++k)
                sum = fmaf(load_full(Ahi, Alo, afrag_idx(row, k)), Wos[2 * k + cc], sum);
            red[idx * 32 + p] = sum;
        }
        __syncthreads();

        if (tid < MT) {
            int p = tid;
            float bo0 = __ldg(bo + b * 2 + 0);
            float bo1 = __ldg(bo + b * 2 + 1);
            float pre0 = red[0 * 32 + p] + bo0;
            float pre1 = red[1 * 32 + p] + bo1;
            float m0 = pre0 > 0.f ? 1.f : 0.f;
            float m1 = pre1 > 0.f ? 1.f : 0.f;
            float J00 = red[2 * 32 + p] * m0;
            float J10 = red[3 * 32 + p] * m1;
            float J01 = red[4 * 32 + p] * m0;
            float J11 = red[5 * 32 + p] * m1;
            float v0 = vv[2 * p], v1 = vv[2 * p + 1];
            float w0 = v0, w1 = v1;
            float ldet = 0.f;
            const float coefs[5] = {1.f, -0.5f, 1.f / 3.f, -0.25f, 0.2f};
            #pragma unroll
            for (int k = 0; k < 5; ++k) {
                float nw0 = fmaf(J00, w0, J01 * w1);
                float nw1 = fmaf(J10, w0, J11 * w1);
                w0 = nw0; w1 = nw1;
                ldet = fmaf(coefs[k], fmaf(w0, v0, w1 * v1), ldet);
            }
            dl[p] -= ldet;
            zx[2 * p]     += fmaxf(pre0, 0.f);
            zx[2 * p + 1] += fmaxf(pre1, 0.f);
        }
        __syncthreads();
    }

    if (tid < MT) {
        int g = pbase + tid;
        out[2 * g]         = zx[2 * tid];
        out[2 * g + 1]     = zx[2 * tid + 1];
        out[2 * B_PTS + g] = dl[tid];
    }
}

extern "C" void kernel_launch(void* const* d_in, const int* in_sizes, int n_in,
                              void* d_out, int out_size)
{
    const float* x  = (const float*)d_in[0];
    const float* v  = (const float*)d_in[1];
    const float* Wi = (const float*)d_in[2];
    const float* bi = (const float*)d_in[3];
    const float* Wm = (const float*)d_in[4];
    const float* bm = (const float*)d_in[5];
    const float* Wo = (const float*)d_in[6];
    const float* bo = (const float*)d_in[7];
    float* out = (float*)d_out;

    prep_w_kernel<<<NLAYERS * NCHUNK * 32 * 32 / 256, 256>>>(Wm);

    cudaFuncSetAttribute(eq_resflow_mma,
                         cudaFuncAttributeMaxDynamicSharedMemorySize, SMEM_BYTES);
    eq_resflow_mma<<<B_PTS / MT, NTHREADS, SMEM_BYTES>>>(x, v, Wi, bi, bm, Wo, bo, out);
}

// round 8
// speedup vs baseline: 3.0465x; 3.0465x over previous
#include <cuda_runtime.h>
#include <cuda_fp16.h>
#include <cstdint>

#define B_PTS   131072
#define HDIM    256
#define NBLK    8
#define NMID    3
#define MT      32
#define NTHREADS 256
#define NLAYERS (NBLK * NMID)

// tangent-state scaling (exact powers of two; divided out of J at the end)
#define TS_SEED   16384.f          // 2^14 applied to tangent seed at layer 0
#define TS_LAYER  16.f             // 2^4 applied at each of the 3 mid-layer epilogues
#define TS_INV    (1.f / 67108864.f)   // 2^-26 = 1/(2^14 * 2^12)

// ---------------- shared memory byte map ----------------
#define OFF_AHI  0            // A hi frags: 6mt x 16ks x 32lane x 16B = 49152
#define OFF_ALO  49152        // A lo frags (unscaled fp16 residual)   = 49152
#define OFF_WOS  98304        // 512 floats = 2048 B
#define OFF_ZX   100352       // 64 floats
#define OFF_VV   100608       // 64 floats
#define OFF_DL   100864       // 32 floats
#define OFF_RED  100992       // 192 floats
#define SMEM_BYTES 101760

// prepacked B fragments: [layer][ks 16][ntile 32][lane 32] x uint4 {b0hi,b1hi,b0lo,b1lo}
__device__ uint4 g_Wf[(size_t)NLAYERS * 16 * 32 * 32];

// ---------------- helpers ----------------
__device__ __forceinline__ void mma_f16(float c[4], const uint4& a, uint32_t b0, uint32_t b1) {
    asm volatile("mma.sync.aligned.m16n8k16.row.col.f32.f16.f16.f32 "
                 "{%0,%1,%2,%3}, {%4,%5,%6,%7}, {%8,%9}, {%0,%1,%2,%3};"
                 : "+f"(c[0]), "+f"(c[1]), "+f"(c[2]), "+f"(c[3])
                 : "r"(a.x), "r"(a.y), "r"(a.z), "r"(a.w), "r"(b0), "r"(b1));
}
__device__ __forceinline__ uint32_t h2u(__half a, __half b) {
    __half2 h = __halves2half2(a, b);
    return *reinterpret_cast<uint32_t*>(&h);
}
// byte offset of element (row 0..95, k 0..255) inside the A fragment image
__device__ __forceinline__ int abyte(int row, int k) {
    int tile = (row >> 4) * 16 + (k >> 4);
    int lane = ((row & 7) << 2) | ((k >> 1) & 3);
    int sub  = ((row & 8) >> 2) | ((k & 8) >> 1) | (k & 1);
    return tile * 512 + lane * 16 + sub * 2;
}
__device__ __forceinline__ void split_store(char* base_hi, char* base_lo, int boff, float v) {
    __half h = __float2half_rn(v);
    __half l = __float2half_rn(v - __half2float(h));
    *(__half*)(base_hi + boff) = h;
    *(__half*)(base_lo + boff) = l;
}

// ---------------- pre-pass: pack Wm into split fp16 B-fragment image ----------------
__global__ void prep_w_kernel(const float* __restrict__ Wm) {
    int g = blockIdx.x * 256 + threadIdx.x;     // 0 .. 393215
    int lane = g & 31;
    int t = g >> 5;
    int ntile = t & 31; t >>= 5;
    int ks    = t & 15; t >>= 4;
    int l     = t;                               // 0..23
    int n  = ntile * 8 + (lane >> 2);
    int kb = ks * 16 + 2 * (lane & 3);
    const float* W = Wm + (size_t)l * HDIM * HDIM;
    __half hh[4], ll[4];
    int kk[4] = {kb, kb + 1, kb + 8, kb + 9};
    #pragma unroll
    for (int i = 0; i < 4; ++i) {
        float w = W[(size_t)kk[i] * HDIM + n];
        hh[i] = __float2half_rn(w);
        ll[i] = __float2half_rn(w - __half2float(hh[i]));
    }
    uint4 o;
    o.x = h2u(hh[0], hh[1]);   // b0 hi (k, k+1)
    o.y = h2u(hh[2], hh[3]);   // b1 hi (k+8, k+9)
    o.z = h2u(ll[0], ll[1]);   // b0 lo
    o.w = h2u(ll[2], ll[3]);   // b1 lo
    g_Wf[g] = o;
}

// ---------------- main kernel ----------------
__global__ void __launch_bounds__(NTHREADS, 1)
eq_resflow_f16(const float* __restrict__ x,  const float* __restrict__ v,
               const float* __restrict__ Wi, const float* __restrict__ bi,
               const float* __restrict__ bm,
               const float* __restrict__ Wo, const float* __restrict__ bo,
               float* __restrict__ out)
{
    extern __shared__ char smem[];
    char* Ahi = smem + OFF_AHI;
    char* Alo = smem + OFF_ALO;
    float* Wos = (float*)(smem + OFF_WOS);
    float* zx  = (float*)(smem + OFF_ZX);
    float* vv  = (float*)(smem + OFF_VV);
    float* dl  = (float*)(smem + OFF_DL);
    float* red = (float*)(smem + OFF_RED);

    const int tid  = threadIdx.x;
    const int w    = tid >> 5;
    const int lane = tid & 31;
    const int pbase = blockIdx.x * MT;

    if (tid < MT) {
        float2 xx = *reinterpret_cast<const float2*>(x + 2 * (pbase + tid));
        float2 vx = *reinterpret_cast<const float2*>(v + 2 * (pbase + tid));
        zx[2 * tid] = xx.x; zx[2 * tid + 1] = xx.y;
        vv[2 * tid] = vx.x; vv[2 * tid + 1] = vx.y;
        dl[tid] = 0.f;
    }
    __syncthreads();

    for (int b = 0; b < NBLK; ++b) {
        // ---------- layer 0 : 2 -> 256, split-write A fragments (tangents scaled 2^14) ----------
        {
            int n = tid;
            float w0 = __ldg(Wi + (size_t)b * 2 * HDIM + n);
            float w1 = __ldg(Wi + (size_t)b * 2 * HDIM + HDIM + n);
            float bb = __ldg(bi + (size_t)b * HDIM + n);
            #pragma unroll 4
            for (int p = 0; p < MT; ++p) {
                float pre = fmaf(zx[2 * p], w0, fmaf(zx[2 * p + 1], w1, bb));
                float m = pre > 0.f ? 1.f : 0.f;
                split_store(Ahi, Alo, abyte(p,      n), fmaxf(pre, 0.f));
                split_store(Ahi, Alo, abyte(32 + p, n), w0 * m * TS_SEED);
                split_store(Ahi, Alo, abyte(64 + p, n), w1 * m * TS_SEED);
            }
        }
        __syncthreads();   // A ready

        // ---------- 3 mid layers : compensated fp16 mma, B direct from L2 ----------
        for (int lj = 0; lj < NMID; ++lj) {
            const int glayer = b * NMID + lj;
            const uint4* Bg = g_Wf + ((size_t)glayer * 16) * 1024 + (w * 4) * 32 + lane;

            float c[6][4][4];
            #pragma unroll
            for (int mt = 0; mt < 6; ++mt)
                #pragma unroll
                for (int ntl = 0; ntl < 4; ++ntl)
                    #pragma unroll
                    for (int r = 0; r < 4; ++r) c[mt][ntl][r] = 0.f;

            uint4 bv[4];
            #pragma unroll
            for (int ntl = 0; ntl < 4; ++ntl) bv[ntl] = __ldg(Bg + ntl * 32);

            #pragma unroll 1
            for (int ks = 0; ks < 16; ++ks) {
                uint4 bn[4];
                if (ks < 15) {
                    const uint4* Bn = Bg + (ks + 1) * 1024;
                    #pragma unroll
                    for (int ntl = 0; ntl < 4; ++ntl) bn[ntl] = __ldg(Bn + ntl * 32);
                }
                #pragma unroll
                for (int mt = 0; mt < 6; ++mt) {
                    const int fo = ((mt * 16 + ks) * 32 + lane) * 16;
                    uint4 ah = *(const uint4*)(Ahi + fo);
                    uint4 al = *(const uint4*)(Alo + fo);
                    #pragma unroll
                    for (int ntl = 0; ntl < 4; ++ntl) {
                        mma_f16(c[mt][ntl], ah, bv[ntl].x, bv[ntl].y);   // hi*hi
                        mma_f16(c[mt][ntl], ah, bv[ntl].z, bv[ntl].w);   // hi*lo
                        mma_f16(c[mt][ntl], al, bv[ntl].x, bv[ntl].y);   // lo*hi
                    }
                }
                #pragma unroll
                for (int ntl = 0; ntl < 4; ++ntl) bv[ntl] = bn[ntl];
            }

            // biases for my 4 n-tiles (col pair 2*(lane&3), +1)
            float2 bb2[4];
            #pragma unroll
            for (int ntl = 0; ntl < 4; ++ntl) {
                int n0 = (w * 4 + ntl) * 8 + 2 * (lane & 3);
                bb2[ntl] = *reinterpret_cast<const float2*>(bm + (size_t)glayer * HDIM + n0);
            }
            __syncthreads();   // all warps done reading A

            // epilogue: bias + ReLU on h, mask tangents (rescaled x16), split-write A
            #pragma unroll
            for (int mt = 0; mt < 2; ++mt) {
                #pragma unroll
                for (int ntl = 0; ntl < 4; ++ntl) {
                    int colb = (w * 4 + ntl) * 8 + 2 * (lane & 3);
                    float pre0 = c[mt][ntl][0] + bb2[ntl].x;
                    float pre1 = c[mt][ntl][1] + bb2[ntl].y;
                    float pre2 = c[mt][ntl][2] + bb2[ntl].x;
                    float pre3 = c[mt][ntl][3] + bb2[ntl].y;
                    float m0 = (pre0 > 0.f ? 1.f : 0.f) * TS_LAYER;
                    float m1 = (pre1 > 0.f ? 1.f : 0.f) * TS_LAYER;
                    float m2 = (pre2 > 0.f ? 1.f : 0.f) * TS_LAYER;
                    float m3 = (pre3 > 0.f ? 1.f : 0.f) * TS_LAYER;
                    // base byte offset for (row=mt*16+(lane>>2), colb); rows+8 are bytes +4
                    int base = (mt * 16 + (colb >> 4)) * 512 + lane * 16 + (colb & 8);
                    float vals[3][4] = {
                        {fmaxf(pre0,0.f), fmaxf(pre1,0.f), fmaxf(pre2,0.f), fmaxf(pre3,0.f)},
                        {c[mt+2][ntl][0]*m0, c[mt+2][ntl][1]*m1, c[mt+2][ntl][2]*m2, c[mt+2][ntl][3]*m3},
                        {c[mt+4][ntl][0]*m0, c[mt+4][ntl][1]*m1, c[mt+4][ntl][2]*m2, c[mt+4][ntl][3]*m3}
                    };
                    #pragma unroll
                    for (int s = 0; s < 3; ++s) {
                        __half h0 = __float2half_rn(vals[s][0]);
                        __half h1 = __float2half_rn(vals[s][1]);
                        __half h2 = __float2half_rn(vals[s][2]);
                        __half h3 = __float2half_rn(vals[s][3]);
                        uint2 hi, lo;
                        hi.x = h2u(h0, h1); hi.y = h2u(h2, h3);
                        lo.x = h2u(__float2half_rn(vals[s][0] - __half2float(h0)),
                                   __float2half_rn(vals[s][1] - __half2float(h1)));
                        lo.y = h2u(__float2half_rn(vals[s][2] - __half2float(h2)),
                                   __float2half_rn(vals[s][3] - __half2float(h3)));
                        int o = base + s * 16384;   // state stride = 2x16 tiles x 512 B
                        *(uint2*)(Ahi + o) = hi;
                        *(uint2*)(Alo + o) = lo;
                    }
                }
            }
            __syncthreads();
        }

        // ---------- output layer : 256 -> 2, Jacobian, power series ----------
        if (tid < 128)
            ((float4*)Wos)[tid] = ((const float4*)(Wo + (size_t)b * HDIM * 2))[tid];
        __syncthreads();

        if (tid < 192) {   // 32 pts x 3 states x 2 cols
            int p = tid & 31, idx = tid >> 5;
            int s = idx >> 1, cc = idx & 1;
            int row = s * 32 + p;
            float sum = 0.f;
            #pragma unroll 4
            for (int k = 0; k < HDIM; k += 2) {
                int o = abyte(row, k);
                __half2 h2 = *(const __half2*)(Ahi + o);
                __half2 l2 = *(const __half2*)(Alo + o);
                float2 hf = __half22float2(h2);
                float2 lf = __half22float2(l2);
                sum = fmaf(hf.x + lf.x, Wos[2 * k + cc], sum);
                sum = fmaf(hf.y + lf.y, Wos[2 * (k + 1) + cc], sum);
            }
            red[idx * 32 + p] = sum;
        }
        __syncthreads();

        if (tid < MT) {
            int p = tid;
            float bo0 = __ldg(bo + b * 2 + 0);
            float bo1 = __ldg(bo + b * 2 + 1);
            float pre0 = red[0 * 32 + p] + bo0;
            float pre1 = red[1 * 32 + p] + bo1;
            float m0 = pre0 > 0.f ? 1.f : 0.f;
            float m1 = pre1 > 0.f ? 1.f : 0.f;
            // tangent reductions carry the 2^26 state scale; divide it out (exact)
            float J00 = red[2 * 32 + p] * m0 * TS_INV;
            float J10 = red[3 * 32 + p] * m1 * TS_INV;
            float J01 = red[4 * 32 + p] * m0 * TS_INV;
            float J11 = red[5 * 32 + p] * m1 * TS_INV;
            float v0 = vv[2 * p], v1 = vv[2 * p + 1];
            float w0 = v0, w1 = v1;
            float ldet = 0.f;
            const float coefs[5] = {1.f, -0.5f, 1.f / 3.f, -0.25f, 0.2f};
            #pragma unroll
            for (int k = 0; k < 5; ++k) {
                float nw0 = fmaf(J00, w0, J01 * w1);
                float nw1 = fmaf(J10, w0, J11 * w1);
                w0 = nw0; w1 = nw1;
                ldet = fmaf(coefs[k], fmaf(w0, v0, w1 * v1), ldet);
            }
            dl[p] -= ldet;
            zx[2 * p]     += fmaxf(pre0, 0.f);
            zx[2 * p + 1] += fmaxf(pre1, 0.f);
        }
        __syncthreads();
    }

    if (tid < MT) {
        int g = pbase + tid;
        out[2 * g]         = zx[2 * tid];
        out[2 * g + 1]     = zx[2 * tid + 1];
        out[2 * B_PTS + g] = dl[tid];
    }
}

extern "C" void kernel_launch(void* const* d_in, const int* in_sizes, int n_in,
                              void* d_out, int out_size)
{
    const float* x  = (const float*)d_in[0];
    const float* v  = (const float*)d_in[1];
    const float* Wi = (const float*)d_in[2];
    const float* bi = (const float*)d_in[3];
    const float* Wm = (const float*)d_in[4];
    const float* bm = (const float*)d_in[5];
    const float* Wo = (const float*)d_in[6];
    const float* bo = (const float*)d_in[7];
    float* out = (float*)d_out;

    prep_w_kernel<<<NLAYERS * 16 * 32 * 32 / 256, 256>>>(Wm);

    cudaFuncSetAttribute(eq_resflow_f16,
                         cudaFuncAttributeMaxDynamicSharedMemorySize, SMEM_BYTES);
    eq_resflow_f16<<<B_PTS / MT, NTHREADS, SMEM_BYTES>>>(x, v, Wi, bi, bm, Wo, bo, out);
}

// round 9
// speedup vs baseline: 3.1073x; 1.0200x over previous
#include <cuda_runtime.h>
#include <cuda_fp16.h>
#include <cstdint>

#define B_PTS   131072
#define HDIM    256
#define NBLK    8
#define NMID    3
#define MT      32
#define NTHREADS 512
#define NLAYERS (NBLK * NMID)

// tangent-state scaling (exact powers of two; divided out of J at the end)
#define TS_SEED   16384.f          // 2^14 applied to tangent seed at layer 0
#define TS_LAYER  16.f             // 2^4 applied at each of the 3 mid-layer epilogues
#define TS_INV    (1.f / 67108864.f)   // 2^-26 = 1/(2^14 * 2^12)

// ---------------- shared memory byte map ----------------
#define OFF_AHI  0            // A hi frags: 6mt x 16ks x 32lane x 16B = 49152
#define OFF_ALO  49152        // A lo frags (unscaled fp16 residual)   = 49152
#define OFF_WOS  98304        // 512 floats = 2048 B
#define OFF_ZX   100352       // 64 floats
#define OFF_VV   100608       // 64 floats
#define OFF_DL   100864       // 32 floats
#define OFF_RED  100992       // 192 floats
#define SMEM_BYTES 101760

// prepacked B fragments: [layer][ks 16][ntile 32][lane 32] x uint4 {b0hi,b1hi,b0lo,b1lo}
__device__ uint4 g_Wf[(size_t)NLAYERS * 16 * 32 * 32];

// ---------------- helpers ----------------
__device__ __forceinline__ void mma_f16(float c[4], const uint4& a, uint32_t b0, uint32_t b1) {
    asm volatile("mma.sync.aligned.m16n8k16.row.col.f32.f16.f16.f32 "
                 "{%0,%1,%2,%3}, {%4,%5,%6,%7}, {%8,%9}, {%0,%1,%2,%3};"
                 : "+f"(c[0]), "+f"(c[1]), "+f"(c[2]), "+f"(c[3])
                 : "r"(a.x), "r"(a.y), "r"(a.z), "r"(a.w), "r"(b0), "r"(b1));
}
__device__ __forceinline__ uint32_t h2u(__half a, __half b) {
    __half2 h = __halves2half2(a, b);
    return *reinterpret_cast<uint32_t*>(&h);
}
// byte offset of element (row 0..95, k 0..255) inside the A fragment image
__device__ __forceinline__ int abyte(int row, int k) {
    int tile = (row >> 4) * 16 + (k >> 4);
    int lane = ((row & 7) << 2) | ((k >> 1) & 3);
    int sub  = ((row & 8) >> 2) | ((k & 8) >> 1) | (k & 1);
    return tile * 512 + lane * 16 + sub * 2;
}
__device__ __forceinline__ void split_store(char* base_hi, char* base_lo, int boff, float v) {
    __half h = __float2half_rn(v);
    __half l = __float2half_rn(v - __half2float(h));
    *(__half*)(base_hi + boff) = h;
    *(__half*)(base_lo + boff) = l;
}

// ---------------- pre-pass: pack Wm into split fp16 B-fragment image ----------------
__global__ void prep_w_kernel(const float* __restrict__ Wm) {
    int g = blockIdx.x * 256 + threadIdx.x;     // 0 .. 393215
    int lane = g & 31;
    int t = g >> 5;
    int ntile = t & 31; t >>= 5;
    int ks    = t & 15; t >>= 4;
    int l     = t;                               // 0..23
    int n  = ntile * 8 + (lane >> 2);
    int kb = ks * 16 + 2 * (lane & 3);
    const float* W = Wm + (size_t)l * HDIM * HDIM;
    __half hh[4], ll[4];
    int kk[4] = {kb, kb + 1, kb + 8, kb + 9};
    #pragma unroll
    for (int i = 0; i < 4; ++i) {
        float w = W[(size_t)kk[i] * HDIM + n];
        hh[i] = __float2half_rn(w);
        ll[i] = __float2half_rn(w - __half2float(hh[i]));
    }
    uint4 o;
    o.x = h2u(hh[0], hh[1]);   // b0 hi (k, k+1)
    o.y = h2u(hh[2], hh[3]);   // b1 hi (k+8, k+9)
    o.z = h2u(ll[0], ll[1]);   // b0 lo
    o.w = h2u(ll[2], ll[3]);   // b1 lo
    g_Wf[g] = o;
}

// ---------------- main kernel ----------------
__global__ void __launch_bounds__(NTHREADS, 1)
eq_resflow_f16(const float* __restrict__ x,  const float* __restrict__ v,
               const float* __restrict__ Wi, const float* __restrict__ bi,
               const float* __restrict__ bm,
               const float* __restrict__ Wo, const float* __restrict__ bo,
               float* __restrict__ out)
{
    extern __shared__ char smem[];
    char* Ahi = smem + OFF_AHI;
    char* Alo = smem + OFF_ALO;
    float* Wos = (float*)(smem + OFF_WOS);
    float* zx  = (float*)(smem + OFF_ZX);
    float* vv  = (float*)(smem + OFF_VV);
    float* dl  = (float*)(smem + OFF_DL);
    float* red = (float*)(smem + OFF_RED);

    const int tid  = threadIdx.x;
    const int w    = tid >> 5;        // 0..15, each owns 2 n-tiles
    const int lane = tid & 31;
    const int pbase = blockIdx.x * MT;

    if (tid < MT) {
        float2 xx = *reinterpret_cast<const float2*>(x + 2 * (pbase + tid));
        float2 vx = *reinterpret_cast<const float2*>(v + 2 * (pbase + tid));
        zx[2 * tid] = xx.x; zx[2 * tid + 1] = xx.y;
        vv[2 * tid] = vx.x; vv[2 * tid + 1] = vx.y;
        dl[tid] = 0.f;
    }
    __syncthreads();

    for (int b = 0; b < NBLK; ++b) {
        // ---------- layer 0 : 2 -> 256, split-write A frags (tangents scaled 2^14) ----------
        {
            int n = tid & 255;
            int p0 = (tid >> 8) * 16;     // threads 0-255 -> pts 0-15, 256-511 -> 16-31
            float w0 = __ldg(Wi + (size_t)b * 2 * HDIM + n);
            float w1 = __ldg(Wi + (size_t)b * 2 * HDIM + HDIM + n);
            float bb = __ldg(bi + (size_t)b * HDIM + n);
            #pragma unroll 4
            for (int pi = 0; pi < 16; ++pi) {
                int p = p0 + pi;
                float pre = fmaf(zx[2 * p], w0, fmaf(zx[2 * p + 1], w1, bb));
                float m = pre > 0.f ? 1.f : 0.f;
                split_store(Ahi, Alo, abyte(p,      n), fmaxf(pre, 0.f));
                split_store(Ahi, Alo, abyte(32 + p, n), w0 * m * TS_SEED);
                split_store(Ahi, Alo, abyte(64 + p, n), w1 * m * TS_SEED);
            }
        }
        __syncthreads();   // A ready

        // ---------- 3 mid layers : compensated fp16 mma, B direct from L2 ----------
        for (int lj = 0; lj < NMID; ++lj) {
            const int glayer = b * NMID + lj;
            const uint4* Bg = g_Wf + ((size_t)glayer * 16) * 1024 + (w * 2) * 32 + lane;

            float c[6][2][4];
            #pragma unroll
            for (int mt = 0; mt < 6; ++mt)
                #pragma unroll
                for (int ntl = 0; ntl < 2; ++ntl)
                    #pragma unroll
                    for (int r = 0; r < 4; ++r) c[mt][ntl][r] = 0.f;

            uint4 bv[2];
            #pragma unroll
            for (int ntl = 0; ntl < 2; ++ntl) bv[ntl] = __ldg(Bg + ntl * 32);

            #pragma unroll 1
            for (int ks = 0; ks < 16; ++ks) {
                uint4 bn[2];
                if (ks < 15) {
                    const uint4* Bn = Bg + (ks + 1) * 1024;
                    #pragma unroll
                    for (int ntl = 0; ntl < 2; ++ntl) bn[ntl] = __ldg(Bn + ntl * 32);
                }
                #pragma unroll
                for (int mt = 0; mt < 6; ++mt) {
                    const int fo = ((mt * 16 + ks) * 32 + lane) * 16;
                    uint4 ah = *(const uint4*)(Ahi + fo);
                    uint4 al = *(const uint4*)(Alo + fo);
                    #pragma unroll
                    for (int ntl = 0; ntl < 2; ++ntl) {
                        mma_f16(c[mt][ntl], ah, bv[ntl].x, bv[ntl].y);   // hi*hi
                        mma_f16(c[mt][ntl], ah, bv[ntl].z, bv[ntl].w);   // hi*lo
                        mma_f16(c[mt][ntl], al, bv[ntl].x, bv[ntl].y);   // lo*hi
                    }
                }
                #pragma unroll
                for (int ntl = 0; ntl < 2; ++ntl) bv[ntl] = bn[ntl];
            }

            // biases for my 2 n-tiles (col pair 2*(lane&3), +1)
            float2 bb2[2];
            #pragma unroll
            for (int ntl = 0; ntl < 2; ++ntl) {
                int n0 = (w * 2 + ntl) * 8 + 2 * (lane & 3);
                bb2[ntl] = *reinterpret_cast<const float2*>(bm + (size_t)glayer * HDIM + n0);
            }
            __syncthreads();   // all warps done reading A

            // epilogue: bias + ReLU on h, mask tangents (rescaled x16), split-write A
            #pragma unroll
            for (int mt = 0; mt < 2; ++mt) {
                #pragma unroll
                for (int ntl = 0; ntl < 2; ++ntl) {
                    int colb = (w * 2 + ntl) * 8 + 2 * (lane & 3);
                    float pre0 = c[mt][ntl][0] + bb2[ntl].x;
                    float pre1 = c[mt][ntl][1] + bb2[ntl].y;
                    float pre2 = c[mt][ntl][2] + bb2[ntl].x;
                    float pre3 = c[mt][ntl][3] + bb2[ntl].y;
                    float m0 = (pre0 > 0.f ? 1.f : 0.f) * TS_LAYER;
                    float m1 = (pre1 > 0.f ? 1.f : 0.f) * TS_LAYER;
                    float m2 = (pre2 > 0.f ? 1.f : 0.f) * TS_LAYER;
                    float m3 = (pre3 > 0.f ? 1.f : 0.f) * TS_LAYER;
                    // base byte offset for (row=mt*16+(lane>>2), colb); rows+8 are bytes +4
                    int base = (mt * 16 + (colb >> 4)) * 512 + lane * 16 + (colb & 8);
                    float vals[3][4] = {
                        {fmaxf(pre0,0.f), fmaxf(pre1,0.f), fmaxf(pre2,0.f), fmaxf(pre3,0.f)},
                        {c[mt+2][ntl][0]*m0, c[mt+2][ntl][1]*m1, c[mt+2][ntl][2]*m2, c[mt+2][ntl][3]*m3},
                        {c[mt+4][ntl][0]*m0, c[mt+4][ntl][1]*m1, c[mt+4][ntl][2]*m2, c[mt+4][ntl][3]*m3}
                    };
                    #pragma unroll
                    for (int s = 0; s < 3; ++s) {
                        __half h0 = __float2half_rn(vals[s][0]);
                        __half h1 = __float2half_rn(vals[s][1]);
                        __half h2 = __float2half_rn(vals[s][2]);
                        __half h3 = __float2half_rn(vals[s][3]);
                        uint2 hi, lo;
                        hi.x = h2u(h0, h1); hi.y = h2u(h2, h3);
                        lo.x = h2u(__float2half_rn(vals[s][0] - __half2float(h0)),
                                   __float2half_rn(vals[s][1] - __half2float(h1)));
                        lo.y = h2u(__float2half_rn(vals[s][2] - __half2float(h2)),
                                   __float2half_rn(vals[s][3] - __half2float(h3)));
                        int o = base + s * 16384;   // state stride = 2x16 tiles x 512 B
                        *(uint2*)(Ahi + o) = hi;
                        *(uint2*)(Alo + o) = lo;
                    }
                }
            }
            __syncthreads();
        }

        // ---------- output layer : 256 -> 2, Jacobian, power series ----------
        if (tid < 128)
            ((float4*)Wos)[tid] = ((const float4*)(Wo + (size_t)b * HDIM * 2))[tid];
        __syncthreads();

        if (tid < 192) {   // 32 pts x 3 states x 2 cols
            int p = tid & 31, idx = tid >> 5;
            int s = idx >> 1, cc = idx & 1;
            int row = s * 32 + p;
            float sum = 0.f;
            #pragma unroll 4
            for (int k = 0; k < HDIM; k += 2) {
                int o = abyte(row, k);
                __half2 h2 = *(const __half2*)(Ahi + o);
                __half2 l2 = *(const __half2*)(Alo + o);
                float2 hf = __half22float2(h2);
                float2 lf = __half22float2(l2);
                sum = fmaf(hf.x + lf.x, Wos[2 * k + cc], sum);
                sum = fmaf(hf.y + lf.y, Wos[2 * (k + 1) + cc], sum);
            }
            red[idx * 32 + p] = sum;
        }
        __syncthreads();

        if (tid < MT) {
            int p = tid;
            float bo0 = __ldg(bo + b * 2 + 0);
            float bo1 = __ldg(bo + b * 2 + 1);
            float pre0 = red[0 * 32 + p] + bo0;
            float pre1 = red[1 * 32 + p] + bo1;
            float m0 = pre0 > 0.f ? 1.f : 0.f;
            float m1 = pre1 > 0.f ? 1.f : 0.f;
            // tangent reductions carry the 2^26 state scale; divide it out (exact)
            float J00 = red[2 * 32 + p] * m0 * TS_INV;
            float J10 = red[3 * 32 + p] * m1 * TS_INV;
            float J01 = red[4 * 32 + p] * m0 * TS_INV;
            float J11 = red[5 * 32 + p] * m1 * TS_INV;
            float v0 = vv[2 * p], v1 = vv[2 * p + 1];
            float w0 = v0, w1 = v1;
            float ldet = 0.f;
            const float coefs[5] = {1.f, -0.5f, 1.f / 3.f, -0.25f, 0.2f};
            #pragma unroll
            for (int k = 0; k < 5; ++k) {
                float nw0 = fmaf(J00, w0, J01 * w1);
                float nw1 = fmaf(J10, w0, J11 * w1);
                w0 = nw0; w1 = nw1;
                ldet = fmaf(coefs[k], fmaf(w0, v0, w1 * v1), ldet);
            }
            dl[p] -= ldet;
            zx[2 * p]     += fmaxf(pre0, 0.f);
            zx[2 * p + 1] += fmaxf(pre1, 0.f);
        }
        __syncthreads();
    }

    if (tid < MT) {
        int g = pbase + tid;
        out[2 * g]         = zx[2 * tid];
        out[2 * g + 1]     = zx[2 * tid + 1];
        out[2 * B_PTS + g] = dl[tid];
    }
}

extern "C" void kernel_launch(void* const* d_in, const int* in_sizes, int n_in,
                              void* d_out, int out_size)
{
    const float* x  = (const float*)d_in[0];
    const float* v  = (const float*)d_in[1];
    const float* Wi = (const float*)d_in[2];
    const float* bi = (const float*)d_in[3];
    const float* Wm = (const float*)d_in[4];
    const float* bm = (const float*)d_in[5];
    const float* Wo = (const float*)d_in[6];
    const float* bo = (const float*)d_in[7];
    float* out = (float*)d_out;

    prep_w_kernel<<<NLAYERS * 16 * 32 * 32 / 256, 256>>>(Wm);

    cudaFuncSetAttribute(eq_resflow_f16,
                         cudaFuncAttributeMaxDynamicSharedMemorySize, SMEM_BYTES);
    eq_resflow_f16<<<B_PTS / MT, NTHREADS, SMEM_BYTES>>>(x, v, Wi, bi, bm, Wo, bo, out);
}